// round 11
// baseline (speedup 1.0000x reference)
#include <cuda_runtime.h>
#include <math.h>

#define NW 16
#define NEUR 32
#define SIGMA 0.005f
#define OMEGA 15.0f
#define WIN_THRESH 1e-5f
#define M_TAB 2048

// pair table: g_tab2[j] = { f(j/M), f((j+1)/M) }, 16B-aligned for float4 access
__device__ __align__(16) float2 g_tab2[M_TAB + 2];

struct Geo {
    float mean[NW];
    float stdv[NW];
    float mo[NW + 1];
};

__device__ __forceinline__ float fast_sigmoid(float z) {
    return __fdividef(1.0f, 1.0f + __expf(-z));
}

__device__ __forceinline__ float tanh_fast(float z) {
    float r;
    asm("tanh.approx.f32 %0, %1;" : "=f"(r) : "f"(z));
    return r;
}

// One BLOCK (128 threads = 4 warps) per table node; one warp per candidate window.
__global__ void __launch_bounds__(128) build_table_kernel(
    const float* __restrict__ W1,  // [NW,1,NEUR]
    const float* __restrict__ b1,  // [NW,NEUR]
    const float* __restrict__ W2,  // [NW,NEUR,NEUR]
    const float* __restrict__ b2,  // [NW,NEUR]
    const float* __restrict__ W3,  // [NW,NEUR,1]
    const float* __restrict__ b3,  // [NW,1]
    Geo geo)
{
    __shared__ float s_part[4];

    int j = blockIdx.x;                 // 0 .. M_TAB
    int lane = threadIdx.x & 31;
    int wid = threadIdx.x >> 5;         // 0..3

    float x = (float)j * (1.0f / (float)M_TAB);

    // candidate window range (mo[i] = i/16 interior): at most 3 windows
    int ilo = (int)floorf((x - 0.0580f) * 16.0f);
    int ihi = (int)floorf((x + 0.0580f) * 16.0f);
    if (ilo < 0) ilo = 0;
    if (ihi > NW - 1) ihi = NW - 1;

    int i = ilo + wid;
    float contrib = 0.0f;

    if (i <= ihi) {
        float win = fast_sigmoid((x - geo.mo[i]) * (1.0f / SIGMA)) *
                    fast_sigmoid((geo.mo[i + 1] - x) * (1.0f / SIGMA));
        if (win > WIN_THRESH) {
            float xn = (x - geo.mean[i]) / geo.stdv[i];

            // layer 1: lane = neuron
            float h1 = tanh_fast(fmaf(xn, __ldg(&W1[i * NEUR + lane]),
                                      __ldg(&b1[i * NEUR + lane])));

            // layer 2: 4 partial accumulators
            const float* w2 = W2 + i * NEUR * NEUR;
            float acc0 = __ldg(&b2[i * NEUR + lane]);
            float acc1 = 0.0f, acc2 = 0.0f, acc3 = 0.0f;
            #pragma unroll
            for (int a = 0; a < NEUR; a += 4) {
                float ha0 = __shfl_sync(0xFFFFFFFFu, h1, a + 0);
                float ha1 = __shfl_sync(0xFFFFFFFFu, h1, a + 1);
                float ha2 = __shfl_sync(0xFFFFFFFFu, h1, a + 2);
                float ha3 = __shfl_sync(0xFFFFFFFFu, h1, a + 3);
                acc0 = fmaf(ha0, __ldg(&w2[(a + 0) * NEUR + lane]), acc0);
                acc1 = fmaf(ha1, __ldg(&w2[(a + 1) * NEUR + lane]), acc1);
                acc2 = fmaf(ha2, __ldg(&w2[(a + 2) * NEUR + lane]), acc2);
                acc3 = fmaf(ha3, __ldg(&w2[(a + 3) * NEUR + lane]), acc3);
            }
            float acc = (acc0 + acc1) + (acc2 + acc3);

            // layer 3
            float t = tanh_fast(acc) * __ldg(&W3[i * NEUR + lane]);
            #pragma unroll
            for (int off = 16; off > 0; off >>= 1)
                t += __shfl_xor_sync(0xFFFFFFFFu, t, off);

            contrib = win * (t + __ldg(&b3[i]));
        }
    }

    if (lane == 0) s_part[wid] = contrib;
    __syncthreads();

    if (threadIdx.x == 0) {
        float pred = (s_part[0] + s_part[1]) + (s_part[2] + s_part[3]);
        float val = tanhf(OMEGA * x) * pred;   // precise final tanh
        if (j < M_TAB) g_tab2[j].x = val;
        if (j > 0)     g_tab2[j - 1].y = val;
    }

    // allow dependent (interp) grid to start launching
    asm volatile("griddepcontrol.launch_dependents;");
}

// scalar lerp: x in [0,1) guaranteed -> i in [0, M_TAB-1], no clamps
__device__ __forceinline__ float lerp1(float xs, const float2* st) {
    float t = xs * (float)M_TAB;
    int i = __float2int_rd(t);
    float frac = t - (float)i;
    float2 p = st[i];
    return fmaf(frac, p.y - p.x, p.x);
}

#define IBLK 256
#define IGRID 1184   // 8 blocks/SM * 148 SMs: exactly one full wave

__global__ void __launch_bounds__(IBLK, 8) interp_kernel(
    const float4* __restrict__ x4,
    float4* __restrict__ out4,
    int n4)
{
    // wait for the build grid's memory to be visible
    asm volatile("griddepcontrol.wait;" ::: "memory");

    __shared__ __align__(16) float2 s_tab[M_TAB];

    // fill pair table via float4 from L2 (L1 may be stale on PDL early launch)
    {
        const float4* gt4 = (const float4*)g_tab2;
        float4* st4 = (float4*)s_tab;
        #pragma unroll
        for (int k = 0; k < 4; k++)
            st4[threadIdx.x + IBLK * k] = __ldcg(&gt4[threadIdx.x + IBLK * k]);
    }
    __syncthreads();

    int idx0 = blockIdx.x * IBLK + threadIdx.x;
    int idx1 = idx0 + IGRID * IBLK;

    float4 xv0, xv1;
    bool v0 = idx0 < n4;
    bool v1 = idx1 < n4;
    if (v0) xv0 = x4[idx0];
    if (v1) xv1 = x4[idx1];

    if (v0) {
        float4 r;
        r.x = lerp1(xv0.x, s_tab);
        r.y = lerp1(xv0.y, s_tab);
        r.z = lerp1(xv0.z, s_tab);
        r.w = lerp1(xv0.w, s_tab);
        out4[idx0] = r;
    }
    if (v1) {
        float4 r;
        r.x = lerp1(xv1.x, s_tab);
        r.y = lerp1(xv1.y, s_tab);
        r.z = lerp1(xv1.z, s_tab);
        r.w = lerp1(xv1.w, s_tab);
        out4[idx1] = r;
    }
}

extern "C" void kernel_launch(void* const* d_in, const int* in_sizes, int n_in,
                              void* d_out, int out_size)
{
    const float* x  = (const float*)d_in[0];
    const float* W1 = (const float*)d_in[1];
    const float* b1 = (const float*)d_in[2];
    const float* W2 = (const float*)d_in[3];
    const float* b2 = (const float*)d_in[4];
    const float* W3 = (const float*)d_in[5];
    const float* b3 = (const float*)d_in[6];
    float* out = (float*)d_out;
    int n = in_sizes[0];

    // geometry (computed in double, cast to float — matches reference)
    Geo geo;
    {
        double dom0 = 0.0, dom1 = 1.0;
        double w = (dom1 - dom0) / NW;
        double overlap = 0.25;
        double sub0[NW], sub1[NW];
        for (int i = 0; i < NW; i++) {
            sub0[i] = (i == 0) ? dom0 : dom0 + ((double)i - overlap / 2.0) * w;
            sub1[i] = (i == NW - 1) ? dom1 : dom0 + ((double)i + 1.0 + overlap / 2.0) * w;
            geo.mean[i] = (float)((sub1[i] + sub0[i]) / 2.0);
            geo.stdv[i] = (float)((sub1[i] - sub0[i]) / 2.0);
        }
        geo.mo[0] = (float)sub0[0];
        geo.mo[NW] = (float)sub1[NW - 1];
        for (int i = 1; i < NW; i++) {
            geo.mo[i] = (float)((sub1[i - 1] + sub0[i]) / 2.0);
        }
    }

    // kernel 1: build pair table, one 128-thread block per node
    build_table_kernel<<<M_TAB + 1, 128>>>(W1, b1, W2, b2, W3, b3, geo);

    // kernel 2: interpolate, launched as a programmatic dependent of kernel 1
    {
        int n4 = n / 4;                       // 524288

        cudaLaunchConfig_t cfg = {};
        cfg.gridDim = dim3(IGRID, 1, 1);
        cfg.blockDim = dim3(IBLK, 1, 1);
        cfg.dynamicSmemBytes = 0;
        cfg.stream = 0;

        cudaLaunchAttribute attrs[1];
        attrs[0].id = cudaLaunchAttributeProgrammaticStreamSerialization;
        attrs[0].val.programmaticStreamSerializationAllowed = 1;
        cfg.attrs = attrs;
        cfg.numAttrs = 1;

        cudaLaunchKernelEx(&cfg, interp_kernel, (const float4*)x, (float4*)out, n4);
    }
}

// round 12
// speedup vs baseline: 1.0200x; 1.0200x over previous
#include <cuda_runtime.h>
#include <math.h>

#define NW 16
#define NEUR 32
#define SIGMA 0.005f
#define OMEGA 15.0f
#define WIN_THRESH 1e-5f
#define M_TAB 2048

// pair table: g_tab2[j] = { f(j/M), f((j+1)/M) }, 16B-aligned for float4 access
__device__ __align__(16) float2 g_tab2[M_TAB + 2];

struct Geo {
    float mean[NW];
    float stdv[NW];
    float mo[NW + 1];
};

__device__ __forceinline__ float fast_sigmoid(float z) {
    return __fdividef(1.0f, 1.0f + __expf(-z));
}

__device__ __forceinline__ float tanh_fast(float z) {
    float r;
    asm("tanh.approx.f32 %0, %1;" : "=f"(r) : "f"(z));
    return r;
}

// One BLOCK (128 threads = 4 warps) per table node; one warp per candidate window.
__global__ void __launch_bounds__(128) build_table_kernel(
    const float* __restrict__ W1,  // [NW,1,NEUR]
    const float* __restrict__ b1,  // [NW,NEUR]
    const float* __restrict__ W2,  // [NW,NEUR,NEUR]
    const float* __restrict__ b2,  // [NW,NEUR]
    const float* __restrict__ W3,  // [NW,NEUR,1]
    const float* __restrict__ b3,  // [NW,1]
    Geo geo)
{
    __shared__ float s_part[4];

    int j = blockIdx.x;                 // 0 .. M_TAB
    int lane = threadIdx.x & 31;
    int wid = threadIdx.x >> 5;         // 0..3

    float x = (float)j * (1.0f / (float)M_TAB);

    // candidate window range (mo[i] = i/16 interior): at most 3 windows
    int ilo = (int)floorf((x - 0.0580f) * 16.0f);
    int ihi = (int)floorf((x + 0.0580f) * 16.0f);
    if (ilo < 0) ilo = 0;
    if (ihi > NW - 1) ihi = NW - 1;

    int i = ilo + wid;
    float contrib = 0.0f;

    if (i <= ihi) {
        float win = fast_sigmoid((x - geo.mo[i]) * (1.0f / SIGMA)) *
                    fast_sigmoid((geo.mo[i + 1] - x) * (1.0f / SIGMA));
        if (win > WIN_THRESH) {
            float xn = (x - geo.mean[i]) / geo.stdv[i];

            // layer 1: lane = neuron
            float h1 = tanh_fast(fmaf(xn, __ldg(&W1[i * NEUR + lane]),
                                      __ldg(&b1[i * NEUR + lane])));

            // layer 2: 4 partial accumulators
            const float* w2 = W2 + i * NEUR * NEUR;
            float acc0 = __ldg(&b2[i * NEUR + lane]);
            float acc1 = 0.0f, acc2 = 0.0f, acc3 = 0.0f;
            #pragma unroll
            for (int a = 0; a < NEUR; a += 4) {
                float ha0 = __shfl_sync(0xFFFFFFFFu, h1, a + 0);
                float ha1 = __shfl_sync(0xFFFFFFFFu, h1, a + 1);
                float ha2 = __shfl_sync(0xFFFFFFFFu, h1, a + 2);
                float ha3 = __shfl_sync(0xFFFFFFFFu, h1, a + 3);
                acc0 = fmaf(ha0, __ldg(&w2[(a + 0) * NEUR + lane]), acc0);
                acc1 = fmaf(ha1, __ldg(&w2[(a + 1) * NEUR + lane]), acc1);
                acc2 = fmaf(ha2, __ldg(&w2[(a + 2) * NEUR + lane]), acc2);
                acc3 = fmaf(ha3, __ldg(&w2[(a + 3) * NEUR + lane]), acc3);
            }
            float acc = (acc0 + acc1) + (acc2 + acc3);

            // layer 3
            float t = tanh_fast(acc) * __ldg(&W3[i * NEUR + lane]);
            #pragma unroll
            for (int off = 16; off > 0; off >>= 1)
                t += __shfl_xor_sync(0xFFFFFFFFu, t, off);

            contrib = win * (t + __ldg(&b3[i]));
        }
    }

    if (lane == 0) s_part[wid] = contrib;
    __syncthreads();

    if (threadIdx.x == 0) {
        float pred = (s_part[0] + s_part[1]) + (s_part[2] + s_part[3]);
        float val = tanhf(OMEGA * x) * pred;   // precise final tanh
        if (j < M_TAB) g_tab2[j].x = val;
        if (j > 0)     g_tab2[j - 1].y = val;
    }
}

// scalar lerp: x in [0,1) guaranteed -> i in [0, M_TAB-1], no clamps
__device__ __forceinline__ float lerp1(float xs, const float2* st) {
    float t = xs * (float)M_TAB;
    int i = __float2int_rd(t);
    float frac = t - (float)i;
    float2 p = st[i];
    return fmaf(frac, p.y - p.x, p.x);
}

__global__ void __launch_bounds__(256) interp_kernel(
    const float4* __restrict__ x4,
    float4* __restrict__ out4,
    int n4)
{
    __shared__ __align__(16) float2 s_tab[M_TAB];

    int idx0 = blockIdx.x * blockDim.x + threadIdx.x;
    int idx1 = idx0 + gridDim.x * blockDim.x;

    // ---- issue x loads FIRST: their ~600cyc DRAM latency overlaps the
    //      table fill below instead of serializing after it ----
    float4 xv0, xv1;
    bool v0 = idx0 < n4;
    bool v1 = idx1 < n4;
    if (v0) xv0 = x4[idx0];
    if (v1) xv1 = x4[idx1];

    // ---- fill pair table via float4: 1024 float4 / 256 threads = 4 each ----
    {
        const float4* gt4 = (const float4*)g_tab2;
        float4* st4 = (float4*)s_tab;
        #pragma unroll
        for (int k = 0; k < 4; k++)
            st4[threadIdx.x + 256 * k] = gt4[threadIdx.x + 256 * k];
    }
    __syncthreads();

    if (v0) {
        float4 r;
        r.x = lerp1(xv0.x, s_tab);
        r.y = lerp1(xv0.y, s_tab);
        r.z = lerp1(xv0.z, s_tab);
        r.w = lerp1(xv0.w, s_tab);
        out4[idx0] = r;
    }
    if (v1) {
        float4 r;
        r.x = lerp1(xv1.x, s_tab);
        r.y = lerp1(xv1.y, s_tab);
        r.z = lerp1(xv1.z, s_tab);
        r.w = lerp1(xv1.w, s_tab);
        out4[idx1] = r;
    }
}

extern "C" void kernel_launch(void* const* d_in, const int* in_sizes, int n_in,
                              void* d_out, int out_size)
{
    const float* x  = (const float*)d_in[0];
    const float* W1 = (const float*)d_in[1];
    const float* b1 = (const float*)d_in[2];
    const float* W2 = (const float*)d_in[3];
    const float* b2 = (const float*)d_in[4];
    const float* W3 = (const float*)d_in[5];
    const float* b3 = (const float*)d_in[6];
    float* out = (float*)d_out;
    int n = in_sizes[0];

    // geometry (computed in double, cast to float — matches reference)
    Geo geo;
    {
        double dom0 = 0.0, dom1 = 1.0;
        double w = (dom1 - dom0) / NW;
        double overlap = 0.25;
        double sub0[NW], sub1[NW];
        for (int i = 0; i < NW; i++) {
            sub0[i] = (i == 0) ? dom0 : dom0 + ((double)i - overlap / 2.0) * w;
            sub1[i] = (i == NW - 1) ? dom1 : dom0 + ((double)i + 1.0 + overlap / 2.0) * w;
            geo.mean[i] = (float)((sub1[i] + sub0[i]) / 2.0);
            geo.stdv[i] = (float)((sub1[i] - sub0[i]) / 2.0);
        }
        geo.mo[0] = (float)sub0[0];
        geo.mo[NW] = (float)sub1[NW - 1];
        for (int i = 1; i < NW; i++) {
            geo.mo[i] = (float)((sub1[i - 1] + sub0[i]) / 2.0);
        }
    }

    // kernel 1: build pair table, one 128-thread block per node (window-parallel)
    build_table_kernel<<<M_TAB + 1, 128>>>(W1, b1, W2, b2, W3, b3, geo);

    // kernel 2: interpolate, 8 elements per thread (R8 config + load reorder)
    {
        int n4 = n / 4;                       // 524288
        int threads = 256;
        int per_grid = threads * 2;
        int blocks = (n4 + per_grid - 1) / per_grid;   // 1024
        interp_kernel<<<blocks, threads>>>((const float4*)x, (float4*)out, n4);
    }
}